// round 16
// baseline (speedup 1.0000x reference)
#include <cuda_runtime.h>
#include <cuda_fp16.h>
#include <cuda_bf16.h>
#include <stdint.h>

#define Nn 100000
#define Ee 1600000
#define Hh 64
#define Gg 128
#define MAXD 64    // per-node CSR bucket capacity (P(deg>=64) ~ 1e-20)
#define POOLC 8    // pool chunks per graph

typedef unsigned long long u64;

// packed node state: bits[40:64) = cnt, bits[0:40) = deg fixed-point (24 frac bits)
#define DEG_SCALE 16777216.0f          // 2^24
#define DEG_MASK  ((1ULL << 40) - 1)

// ---- device scratch ----
__device__ u64   g_cd[Nn];
__device__ int2  g_csr[Nn * MAXD];     // {src, half2(w,w) bits}; zero-padded to mult of 8
__device__ __half g_h[Nn * Hh];        // node features (fp16)
__device__ __half g_hw[Nn * Hh];       // dinv-scaled h @ W (fp16)
__device__ __half g_wt0[64 * 64];      // W0^T fp16, n-major
__device__ __half g_wt1[64 * 64];      // W1^T fp16
__device__ float g_pool[Gg * Hh];      // pooled partial sums

__device__ __forceinline__ float decode_deg(u64 v) {
    return (float)(v & DEG_MASK) * (1.0f / DEG_SCALE);
}
__device__ __forceinline__ int decode_cnt(u64 v) {
    int c = (int)(v >> 40);
    return c < MAXD ? c : MAXD;
}

// init node state (deg=1.0 self loop) + weight transpose/convert + pool zero
__global__ void k_zero(const float* __restrict__ W0, const float* __restrict__ W1) {
    int i = blockIdx.x * blockDim.x + threadIdx.x;
    if (i < Nn) g_cd[i] = (u64)(1u << 24);   // cnt=0, deg=1.0
    if (i < 4096) {
        int k = i >> 6, n = i & 63;
        g_wt0[n * 64 + k] = __float2half(W0[i]);
        g_wt1[n * 64 + k] = __float2half(W1[i]);
    }
    if (i < Gg * Hh) g_pool[i] = 0.0f;
}

// fused: 2 edges/thread; single 64-bit atomic gives slot + weighted degree
__global__ void k_place(const int* __restrict__ ei, const float* __restrict__ ew) {
    int t = blockIdx.x * blockDim.x + threadIdx.x;
    if (t >= Ee / 2) return;
    int2 ss = reinterpret_cast<const int2*>(ei)[t];
    int2 dd = reinterpret_cast<const int2*>(ei + Ee)[t];
    float2 ww = reinterpret_cast<const float2*>(ew)[t];

    {
        u64 inc = (1ULL << 40) | (u64)__float2uint_rn(ww.x * DEG_SCALE);
        u64 old = atomicAdd(&g_cd[dd.x], inc);
        int slot = (int)(old >> 40);
        if (slot < MAXD) {
            __half2 wp = __float2half2_rn(ww.x);
            g_csr[(dd.x << 6) + slot] = make_int2(ss.x, *reinterpret_cast<int*>(&wp));
        }
    }
    {
        u64 inc = (1ULL << 40) | (u64)__float2uint_rn(ww.y * DEG_SCALE);
        u64 old = atomicAdd(&g_cd[dd.y], inc);
        int slot = (int)(old >> 40);
        if (slot < MAXD) {
            __half2 wp = __float2half2_rn(ww.y);
            g_csr[(dd.y << 6) + slot] = make_int2(ss.y, *reinterpret_cast<int*>(&wp));
        }
    }
}

// ---- HMMA m16n8k16 wrapper ----
__device__ __forceinline__ void mma16816(float& d0, float& d1, float& d2, float& d3,
                                         uint32_t a0, uint32_t a1, uint32_t a2, uint32_t a3,
                                         uint32_t b0, uint32_t b1) {
    asm volatile(
        "mma.sync.aligned.m16n8k16.row.col.f32.f16.f16.f32 "
        "{%0,%1,%2,%3}, {%4,%5,%6,%7}, {%8,%9}, {%0,%1,%2,%3};\n"
        : "+f"(d0), "+f"(d1), "+f"(d2), "+f"(d3)
        : "r"(a0), "r"(a1), "r"(a2), "r"(a3), "r"(b0), "r"(b1));
}

// stage fp16 W^T (n-major 64x64) into sWT[64][72] with vector ld/st
__device__ __forceinline__ void fill_wt_fp16(__half (*sWT)[72], const __half* __restrict__ gwt, int tid) {
    #pragma unroll
    for (int i = 0; i < 4; i++) {
        int t = tid + i * 128;
        int n = t >> 3;
        int q = t & 7;
        uint4 v = *reinterpret_cast<const uint4*>(&gwt[n * 64 + q * 8]);
        *reinterpret_cast<uint4*>(&sWT[n][q * 8]) = v;
    }
}

// shared compute: sA[64][72] fp16 rows, sWT[64][72] fp16 (n-major W^T)
__device__ __forceinline__ void gemm_mma_compute(const __half (*sA)[72], const __half (*sWT)[72],
                                                 int rowBase, int tid) {
    int wid = tid >> 5;
    int lane = tid & 31;
    int gid = lane >> 2;
    int tg = lane & 3;
    int r0 = wid * 16 + gid;

    float c[8][4];
    #pragma unroll
    for (int nt = 0; nt < 8; nt++)
        #pragma unroll
        for (int i = 0; i < 4; i++) c[nt][i] = 0.f;

    #pragma unroll
    for (int kc = 0; kc < 4; kc++) {
        int kb = kc * 16 + tg * 2;
        uint32_t a0 = *reinterpret_cast<const uint32_t*>(&sA[r0][kb]);
        uint32_t a1 = *reinterpret_cast<const uint32_t*>(&sA[r0 + 8][kb]);
        uint32_t a2 = *reinterpret_cast<const uint32_t*>(&sA[r0][kb + 8]);
        uint32_t a3 = *reinterpret_cast<const uint32_t*>(&sA[r0 + 8][kb + 8]);
        #pragma unroll
        for (int nt = 0; nt < 8; nt++) {
            uint32_t b0 = *reinterpret_cast<const uint32_t*>(&sWT[nt * 8 + gid][kb]);
            uint32_t b1 = *reinterpret_cast<const uint32_t*>(&sWT[nt * 8 + gid][kb + 8]);
            mma16816(c[nt][0], c[nt][1], c[nt][2], c[nt][3], a0, a1, a2, a3, b0, b1);
        }
    }

    int gr0 = rowBase + r0;
    int gr1 = gr0 + 8;
    float dg0 = decode_deg(g_cd[gr0 < Nn ? gr0 : 0]);
    float dg1 = decode_deg(g_cd[gr1 < Nn ? gr1 : 0]);
    float s0 = (dg0 > 0.f) ? rsqrtf(dg0) : 0.f;
    float s1 = (dg1 > 0.f) ? rsqrtf(dg1) : 0.f;
    #pragma unroll
    for (int nt = 0; nt < 8; nt++) {
        int col = nt * 8 + tg * 2;
        if (gr0 < Nn)
            *reinterpret_cast<__half2*>(&g_hw[gr0 * 64 + col]) =
                __floats2half2_rn(c[nt][0] * s0, c[nt][1] * s0);
        if (gr1 < Nn)
            *reinterpret_cast<__half2*>(&g_hw[gr1 * 64 + col]) =
                __floats2half2_rn(c[nt][2] * s1, c[nt][3] * s1);
    }
}

// pad this block's 64 nodes' csr buckets to multiple of 8 (fused into gemm0)
__device__ __forceinline__ void pad_block(int rowBase, int tid) {
    #pragma unroll
    for (int i = 0; i < 4; i++) {
        int idx = tid + i * 128;        // 0..511 = 64 nodes x 8
        int nl = idx >> 3;
        int j = idx & 7;
        int n = rowBase + nl;
        if (n < Nn) {
            int c = decode_cnt(g_cd[n]);
            int r = (c + 7) & ~7;
            int slot = c + j;
            if (slot < r)
                g_csr[(n << 6) + slot] = make_int2(0, 0);
        }
    }
}

// ---- layer-0 GEMM (tensor core) + csr padding: concat(x, emb[mapping]) @ W0 ----
__global__ void __launch_bounds__(128) k_gemm0(const float* __restrict__ x, const int* __restrict__ mapping,
                        const float* __restrict__ emb) {
    __shared__ __half sA[64][72];
    __shared__ __half sWT[64][72];
    int tid = threadIdx.x;   // 128
    int rowBase = blockIdx.x * 64;

    pad_block(rowBase, tid);
    fill_wt_fp16(sWT, g_wt0, tid);
    #pragma unroll
    for (int i = 0; i < 4; i++) {
        int t = tid + i * 128;
        int r = t >> 3;
        int q = t & 7;
        int gr = rowBase + r;
        float4 v = make_float4(0.f, 0.f, 0.f, 0.f);
        if (gr < Nn) v = reinterpret_cast<const float4*>(x)[gr * 8 + q];
        __half2 p0 = __floats2half2_rn(v.x, v.y);
        __half2 p1 = __floats2half2_rn(v.z, v.w);
        uint2 pk = make_uint2(*reinterpret_cast<uint32_t*>(&p0), *reinterpret_cast<uint32_t*>(&p1));
        *reinterpret_cast<uint2*>(&sA[r][q * 4]) = pk;
    }
    #pragma unroll
    for (int i = 0; i < 4; i++) {
        int t = tid + i * 128;
        int r = t >> 3;
        int q = t & 7;
        int gr = rowBase + r;
        float4 v = make_float4(0.f, 0.f, 0.f, 0.f);
        if (gr < Nn) {
            int m = __ldg(&mapping[gr]);
            v = reinterpret_cast<const float4*>(emb)[m * 8 + q];
        }
        __half2 p0 = __floats2half2_rn(v.x, v.y);
        __half2 p1 = __floats2half2_rn(v.z, v.w);
        uint2 pk = make_uint2(*reinterpret_cast<uint32_t*>(&p0), *reinterpret_cast<uint32_t*>(&p1));
        *reinterpret_cast<uint2*>(&sA[r][32 + q * 4]) = pk;
    }
    __syncthreads();
    gemm_mma_compute(sA, sWT, rowBase, tid);
}

// ---- layer-1 GEMM (tensor core): g_h (fp16) @ W1 ----
__global__ void __launch_bounds__(128) k_gemm1() {
    __shared__ __half sA[64][72];
    __shared__ __half sWT[64][72];
    int tid = threadIdx.x;   // 128
    int rowBase = blockIdx.x * 64;

    fill_wt_fp16(sWT, g_wt1, tid);
    #pragma unroll
    for (int i = 0; i < 4; i++) {
        int t = tid + i * 128;
        int r = t >> 3;
        int q = t & 7;
        int gr = rowBase + r;
        uint4 v = make_uint4(0, 0, 0, 0);
        if (gr < Nn) v = reinterpret_cast<const uint4*>(g_h)[gr * 8 + q];
        *reinterpret_cast<uint4*>(&sA[r][q * 8]) = v;
    }
    __syncthreads();
    gemm_mma_compute(sA, sWT, rowBase, tid);
}

// gather: HALF-WARP per node (2 nodes/warp), 8-edge HFMA2 blocks folded to fp32
__global__ void k_gather(const float* __restrict__ b) {
    int tid = threadIdx.x;          // 256
    int warp = tid >> 5;
    int lane = tid & 31;
    int half = lane >> 4;
    int sub = lane & 15;
    int n = (blockIdx.x * 8 + warp) * 2 + half;   // grid 6250 * 16 = 100000 exactly

    u64 cd = g_cd[n];
    float dg = decode_deg(cd);
    float dinv = (dg > 0.f) ? rsqrtf(dg) : 0.f;
    int cnt = decode_cnt(cd);
    int nb = (cnt + 7) >> 3;

    const char* hwb = reinterpret_cast<const char*>(g_hw);
    int coff = sub * 8;

    uint2 sv = __ldg(reinterpret_cast<const uint2*>(hwb + n * 128 + coff));
    float2 accA = __half22float2(*reinterpret_cast<__half2*>(&sv.x));
    float2 accB = __half22float2(*reinterpret_cast<__half2*>(&sv.y));

    const int4* q = reinterpret_cast<const int4*>(&g_csr[n << 6]);

    for (int ib = 0; ib < nb; ib++) {
        int4 p0 = __ldg(&q[ib * 4 + 0]);
        int4 p1 = __ldg(&q[ib * 4 + 1]);
        int4 p2 = __ldg(&q[ib * 4 + 2]);
        int4 p3 = __ldg(&q[ib * 4 + 3]);
        uint2 v0 = __ldg(reinterpret_cast<const uint2*>(hwb + p0.x * 128 + coff));
        uint2 v1 = __ldg(reinterpret_cast<const uint2*>(hwb + p0.z * 128 + coff));
        uint2 v2 = __ldg(reinterpret_cast<const uint2*>(hwb + p1.x * 128 + coff));
        uint2 v3 = __ldg(reinterpret_cast<const uint2*>(hwb + p1.z * 128 + coff));
        uint2 v4 = __ldg(reinterpret_cast<const uint2*>(hwb + p2.x * 128 + coff));
        uint2 v5 = __ldg(reinterpret_cast<const uint2*>(hwb + p2.z * 128 + coff));
        uint2 v6 = __ldg(reinterpret_cast<const uint2*>(hwb + p3.x * 128 + coff));
        uint2 v7 = __ldg(reinterpret_cast<const uint2*>(hwb + p3.z * 128 + coff));
        __half2 w0 = *reinterpret_cast<__half2*>(&p0.y);
        __half2 w1 = *reinterpret_cast<__half2*>(&p0.w);
        __half2 w2 = *reinterpret_cast<__half2*>(&p1.y);
        __half2 w3 = *reinterpret_cast<__half2*>(&p1.w);
        __half2 w4 = *reinterpret_cast<__half2*>(&p2.y);
        __half2 w5 = *reinterpret_cast<__half2*>(&p2.w);
        __half2 w6 = *reinterpret_cast<__half2*>(&p3.y);
        __half2 w7 = *reinterpret_cast<__half2*>(&p3.w);
        __half2 sA = __hmul2(*reinterpret_cast<__half2*>(&v0.x), w0);
        __half2 sB = __hmul2(*reinterpret_cast<__half2*>(&v0.y), w0);
        sA = __hfma2(*reinterpret_cast<__half2*>(&v1.x), w1, sA);
        sB = __hfma2(*reinterpret_cast<__half2*>(&v1.y), w1, sB);
        sA = __hfma2(*reinterpret_cast<__half2*>(&v2.x), w2, sA);
        sB = __hfma2(*reinterpret_cast<__half2*>(&v2.y), w2, sB);
        sA = __hfma2(*reinterpret_cast<__half2*>(&v3.x), w3, sA);
        sB = __hfma2(*reinterpret_cast<__half2*>(&v3.y), w3, sB);
        sA = __hfma2(*reinterpret_cast<__half2*>(&v4.x), w4, sA);
        sB = __hfma2(*reinterpret_cast<__half2*>(&v4.y), w4, sB);
        sA = __hfma2(*reinterpret_cast<__half2*>(&v5.x), w5, sA);
        sB = __hfma2(*reinterpret_cast<__half2*>(&v5.y), w5, sB);
        sA = __hfma2(*reinterpret_cast<__half2*>(&v6.x), w6, sA);
        sB = __hfma2(*reinterpret_cast<__half2*>(&v6.y), w6, sB);
        sA = __hfma2(*reinterpret_cast<__half2*>(&v7.x), w7, sA);
        sB = __hfma2(*reinterpret_cast<__half2*>(&v7.y), w7, sB);
        float2 fA = __half22float2(sA);
        float2 fB = __half22float2(sB);
        accA.x += fA.x; accA.y += fA.y;
        accB.x += fB.x; accB.y += fB.y;
    }

    float4 bb = reinterpret_cast<const float4*>(b)[sub];
    accA.x = fmaxf(fmaf(accA.x, dinv, bb.x), 0.f);
    accA.y = fmaxf(fmaf(accA.y, dinv, bb.y), 0.f);
    accB.x = fmaxf(fmaf(accB.x, dinv, bb.z), 0.f);
    accB.y = fmaxf(fmaf(accB.y, dinv, bb.w), 0.f);
    __half2 o0 = __floats2half2_rn(accA.x, accA.y);
    __half2 o1 = __floats2half2_rn(accB.x, accB.y);
    uint2 ov = make_uint2(*reinterpret_cast<uint32_t*>(&o0), *reinterpret_cast<uint32_t*>(&o1));
    *reinterpret_cast<uint2*>(reinterpret_cast<char*>(g_h) + n * 128 + coff) = ov;
}

// pool phase 1: 8 chunk-blocks per graph reduce into g_pool via red.global
__global__ void k_poolpart(const int* __restrict__ batch) {
    __shared__ float sh[8][64];
    int g = blockIdx.x >> 3;
    int chunk = blockIdx.x & 7;
    int tid = threadIdx.x;   // 256
    int lo = 0, hi = Nn;
    while (lo < hi) { int mid = (lo + hi) >> 1; if (batch[mid] < g) lo = mid + 1; else hi = mid; }
    int start = lo;
    lo = start; hi = Nn;
    while (lo < hi) { int mid = (lo + hi) >> 1; if (batch[mid] < g + 1) lo = mid + 1; else hi = mid; }
    int end = lo;
    int len = end - start;
    int c0 = start + (len * chunk) / POOLC;
    int c1 = start + (len * (chunk + 1)) / POOLC;

    int col2 = tid & 31;
    int r = tid >> 5;
    const __half2* h2 = reinterpret_cast<const __half2*>(g_h);
    float2 acc = make_float2(0.f, 0.f);
    for (int node = c0 + r; node < c1; node += 8) {
        float2 v = __half22float2(h2[node * 32 + col2]);
        acc.x += v.x; acc.y += v.y;
    }
    sh[r][col2 * 2] = acc.x;
    sh[r][col2 * 2 + 1] = acc.y;
    __syncthreads();
    if (tid < 32) {
        float s0 = 0.f, s1 = 0.f;
        #pragma unroll
        for (int k = 0; k < 8; k++) { s0 += sh[k][tid * 2]; s1 += sh[k][tid * 2 + 1]; }
        float* dst = &g_pool[g * 64 + tid * 2];
        asm volatile("red.global.add.v2.f32 [%0], {%1,%2};" :: "l"(dst), "f"(s0), "f"(s1) : "memory");
    }
}

// pool phase 2: divide by count
__global__ void k_final(const int* __restrict__ batch, float* __restrict__ out) {
    __shared__ int s_cnt;
    int g = blockIdx.x;
    int tid = threadIdx.x;   // 64
    if (tid == 0) {
        int lo = 0, hi = Nn;
        while (lo < hi) { int mid = (lo + hi) >> 1; if (batch[mid] < g) lo = mid + 1; else hi = mid; }
        int start = lo;
        lo = start; hi = Nn;
        while (lo < hi) { int mid = (lo + hi) >> 1; if (batch[mid] < g + 1) lo = mid + 1; else hi = mid; }
        s_cnt = lo - start;
    }
    __syncthreads();
    float cnt = fmaxf((float)s_cnt, 1.0f);
    out[g * 64 + tid] = g_pool[g * 64 + tid] / cnt;
}

extern "C" void kernel_launch(void* const* d_in, const int* in_sizes, int n_in,
                              void* d_out, int out_size) {
    const float* x       = (const float*)d_in[0];
    const int*   mapping = (const int*)d_in[1];
    const int*   ei      = (const int*)d_in[2];
    const float* ew      = (const float*)d_in[3];
    const int*   batch   = (const int*)d_in[4];
    const float* emb     = (const float*)d_in[5];
    const float* W0      = (const float*)d_in[6];
    const float* b0      = (const float*)d_in[7];
    const float* W1      = (const float*)d_in[8];
    const float* b1      = (const float*)d_in[9];
    float* out = (float*)d_out;

    const int T = 256;
    k_zero<<<(Nn + T - 1) / T, T>>>(W0, W1);
    k_place<<<(Ee / 2 + T - 1) / T, T>>>(ei, ew);

    int gemmBlocks = (Nn + 63) / 64;       // 1563
    int gatherBlocks = Nn / 16;            // 6250, exact
    k_gemm0<<<gemmBlocks, 128>>>(x, mapping, emb);   // includes csr padding
    k_gather<<<gatherBlocks, T>>>(b0);

    k_gemm1<<<gemmBlocks, 128>>>();
    k_gather<<<gatherBlocks, T>>>(b1);

    k_poolpart<<<Gg * POOLC, T>>>(batch);
    k_final<<<Gg, 64>>>(batch, out);
}

// round 17
// speedup vs baseline: 1.0355x; 1.0355x over previous
#include <cuda_runtime.h>
#include <cuda_fp16.h>
#include <cuda_bf16.h>
#include <stdint.h>

#define Nn 100000
#define Ee 1600000
#define Hh 64
#define Gg 128
#define MAXD 64    // per-node CSR bucket capacity (P(deg>=64) ~ 1e-20)

typedef unsigned long long u64;

// packed node state: bits[40:64) = cnt, bits[0:40) = deg fixed-point (24 frac bits)
#define DEG_SCALE 16777216.0f          // 2^24
#define DEG_MASK  ((1ULL << 40) - 1)

// ---- device scratch ----
__device__ u64   g_cd[Nn];
__device__ int2  g_csr[Nn * MAXD];     // {src, half2(w,w) bits}; zero-padded to mult of 8
__device__ __half g_h[Nn * Hh];        // node features (fp16)
__device__ __half g_hw[Nn * Hh];       // dinv-scaled h @ W (fp16)
__device__ __half g_wt0[64 * 64];      // W0^T fp16, n-major
__device__ __half g_wt1[64 * 64];      // W1^T fp16

__device__ __forceinline__ float decode_deg(u64 v) {
    return (float)(v & DEG_MASK) * (1.0f / DEG_SCALE);
}
__device__ __forceinline__ int decode_cnt(u64 v) {
    int c = (int)(v >> 40);
    return c < MAXD ? c : MAXD;
}

// init node state (deg=1.0 self loop) + one-time weight transpose/convert
__global__ void k_zero(const float* __restrict__ W0, const float* __restrict__ W1) {
    int i = blockIdx.x * blockDim.x + threadIdx.x;
    if (i < Nn) g_cd[i] = (u64)(1u << 24);   // cnt=0, deg=1.0
    if (i < 4096) {
        int k = i >> 6, n = i & 63;
        g_wt0[n * 64 + k] = __float2half(W0[i]);
        g_wt1[n * 64 + k] = __float2half(W1[i]);
    }
}

// fused: single 64-bit atomic gives slot + accumulates weighted degree
__global__ void k_place(const int* __restrict__ ei, const float* __restrict__ ew) {
    int e = blockIdx.x * blockDim.x + threadIdx.x;
    if (e < Ee) {
        int s = ei[e];
        int d = ei[Ee + e];
        float w = ew[e];
        u64 inc = (1ULL << 40) | (u64)__float2uint_rn(w * DEG_SCALE);
        u64 old = atomicAdd(&g_cd[d], inc);
        int slot = (int)(old >> 40);
        if (slot < MAXD) {
            __half2 wp = __float2half2_rn(w);
            g_csr[(d << 6) + slot] = make_int2(s, *reinterpret_cast<int*>(&wp));
        }
    }
}

// zero-pad buckets to multiple of 8: 8 threads per node, <=1 store each
__global__ void k_pad() {
    int idx = blockIdx.x * blockDim.x + threadIdx.x;
    if (idx >= Nn * 8) return;
    int n = idx >> 3;
    int j = idx & 7;
    int c = decode_cnt(g_cd[n]);
    int r = (c + 7) & ~7;
    int slot = c + j;
    if (slot < r)
        g_csr[(n << 6) + slot] = make_int2(0, 0);
}

// ---- HMMA m16n8k16 wrapper ----
__device__ __forceinline__ void mma16816(float& d0, float& d1, float& d2, float& d3,
                                         uint32_t a0, uint32_t a1, uint32_t a2, uint32_t a3,
                                         uint32_t b0, uint32_t b1) {
    asm volatile(
        "mma.sync.aligned.m16n8k16.row.col.f32.f16.f16.f32 "
        "{%0,%1,%2,%3}, {%4,%5,%6,%7}, {%8,%9}, {%0,%1,%2,%3};\n"
        : "+f"(d0), "+f"(d1), "+f"(d2), "+f"(d3)
        : "r"(a0), "r"(a1), "r"(a2), "r"(a3), "r"(b0), "r"(b1));
}

// stage fp16 W^T (n-major 64x64) into sWT[64][72] with vector ld/st
__device__ __forceinline__ void fill_wt_fp16(__half (*sWT)[72], const __half* __restrict__ gwt, int tid) {
    #pragma unroll
    for (int i = 0; i < 4; i++) {
        int t = tid + i * 128;
        int n = t >> 3;
        int q = t & 7;
        uint4 v = *reinterpret_cast<const uint4*>(&gwt[n * 64 + q * 8]);
        *reinterpret_cast<uint4*>(&sWT[n][q * 8]) = v;
    }
}

// shared compute: sA[64][72] fp16 rows, sWT[64][72] fp16 (n-major W^T)
__device__ __forceinline__ void gemm_mma_compute(const __half (*sA)[72], const __half (*sWT)[72],
                                                 int rowBase, int tid) {
    int wid = tid >> 5;
    int lane = tid & 31;
    int gid = lane >> 2;
    int tg = lane & 3;
    int r0 = wid * 16 + gid;

    float c[8][4];
    #pragma unroll
    for (int nt = 0; nt < 8; nt++)
        #pragma unroll
        for (int i = 0; i < 4; i++) c[nt][i] = 0.f;

    #pragma unroll
    for (int kc = 0; kc < 4; kc++) {
        int kb = kc * 16 + tg * 2;
        uint32_t a0 = *reinterpret_cast<const uint32_t*>(&sA[r0][kb]);
        uint32_t a1 = *reinterpret_cast<const uint32_t*>(&sA[r0 + 8][kb]);
        uint32_t a2 = *reinterpret_cast<const uint32_t*>(&sA[r0][kb + 8]);
        uint32_t a3 = *reinterpret_cast<const uint32_t*>(&sA[r0 + 8][kb + 8]);
        #pragma unroll
        for (int nt = 0; nt < 8; nt++) {
            uint32_t b0 = *reinterpret_cast<const uint32_t*>(&sWT[nt * 8 + gid][kb]);
            uint32_t b1 = *reinterpret_cast<const uint32_t*>(&sWT[nt * 8 + gid][kb + 8]);
            mma16816(c[nt][0], c[nt][1], c[nt][2], c[nt][3], a0, a1, a2, a3, b0, b1);
        }
    }

    int gr0 = rowBase + r0;
    int gr1 = gr0 + 8;
    float dg0 = decode_deg(g_cd[gr0 < Nn ? gr0 : 0]);
    float dg1 = decode_deg(g_cd[gr1 < Nn ? gr1 : 0]);
    float s0 = (dg0 > 0.f) ? rsqrtf(dg0) : 0.f;
    float s1 = (dg1 > 0.f) ? rsqrtf(dg1) : 0.f;
    #pragma unroll
    for (int nt = 0; nt < 8; nt++) {
        int col = nt * 8 + tg * 2;
        if (gr0 < Nn)
            *reinterpret_cast<__half2*>(&g_hw[gr0 * 64 + col]) =
                __floats2half2_rn(c[nt][0] * s0, c[nt][1] * s0);
        if (gr1 < Nn)
            *reinterpret_cast<__half2*>(&g_hw[gr1 * 64 + col]) =
                __floats2half2_rn(c[nt][2] * s1, c[nt][3] * s1);
    }
}

// ---- layer-0 GEMM (tensor core): concat(x, emb[mapping]) @ W0 ----
__global__ void __launch_bounds__(128) k_gemm0(const float* __restrict__ x, const int* __restrict__ mapping,
                        const float* __restrict__ emb) {
    __shared__ __half sA[64][72];
    __shared__ __half sWT[64][72];
    int tid = threadIdx.x;   // 128
    int rowBase = blockIdx.x * 64;

    fill_wt_fp16(sWT, g_wt0, tid);
    #pragma unroll
    for (int i = 0; i < 4; i++) {
        int t = tid + i * 128;
        int r = t >> 3;
        int q = t & 7;
        int gr = rowBase + r;
        float4 v = make_float4(0.f, 0.f, 0.f, 0.f);
        if (gr < Nn) v = reinterpret_cast<const float4*>(x)[gr * 8 + q];
        __half2 p0 = __floats2half2_rn(v.x, v.y);
        __half2 p1 = __floats2half2_rn(v.z, v.w);
        uint2 pk = make_uint2(*reinterpret_cast<uint32_t*>(&p0), *reinterpret_cast<uint32_t*>(&p1));
        *reinterpret_cast<uint2*>(&sA[r][q * 4]) = pk;
    }
    #pragma unroll
    for (int i = 0; i < 4; i++) {
        int t = tid + i * 128;
        int r = t >> 3;
        int q = t & 7;
        int gr = rowBase + r;
        float4 v = make_float4(0.f, 0.f, 0.f, 0.f);
        if (gr < Nn) {
            int m = __ldg(&mapping[gr]);
            v = reinterpret_cast<const float4*>(emb)[m * 8 + q];
        }
        __half2 p0 = __floats2half2_rn(v.x, v.y);
        __half2 p1 = __floats2half2_rn(v.z, v.w);
        uint2 pk = make_uint2(*reinterpret_cast<uint32_t*>(&p0), *reinterpret_cast<uint32_t*>(&p1));
        *reinterpret_cast<uint2*>(&sA[r][32 + q * 4]) = pk;
    }
    __syncthreads();
    gemm_mma_compute(sA, sWT, rowBase, tid);
}

// ---- layer-1 GEMM (tensor core): g_h (fp16) @ W1 ----
__global__ void __launch_bounds__(128) k_gemm1() {
    __shared__ __half sA[64][72];
    __shared__ __half sWT[64][72];
    int tid = threadIdx.x;   // 128
    int rowBase = blockIdx.x * 64;

    fill_wt_fp16(sWT, g_wt1, tid);
    #pragma unroll
    for (int i = 0; i < 4; i++) {
        int t = tid + i * 128;
        int r = t >> 3;
        int q = t & 7;
        int gr = rowBase + r;
        uint4 v = make_uint4(0, 0, 0, 0);
        if (gr < Nn) v = reinterpret_cast<const uint4*>(g_h)[gr * 8 + q];
        *reinterpret_cast<uint4*>(&sA[r][q * 8]) = v;
    }
    __syncthreads();
    gemm_mma_compute(sA, sWT, rowBase, tid);
}

// edge accumulate: row uint4 (8 halfs) x dup weight into 4 half2 chains
__device__ __forceinline__ void edge8(uint4 v, int wbits, __half2& s0, __half2& s1,
                                      __half2& s2, __half2& s3) {
    __half2 w = *reinterpret_cast<__half2*>(&wbits);
    s0 = __hfma2(*reinterpret_cast<__half2*>(&v.x), w, s0);
    s1 = __hfma2(*reinterpret_cast<__half2*>(&v.y), w, s1);
    s2 = __hfma2(*reinterpret_cast<__half2*>(&v.z), w, s2);
    s3 = __hfma2(*reinterpret_cast<__half2*>(&v.w), w, s3);
}

// gather: QUARTER-WARP per node (4 nodes/warp). Each lane covers 8 columns (LDG.128).
// 8-edge blocks, 4x HFMA2 chains folded to fp32 per block; group-uniform guard.
__global__ void k_gather(const float* __restrict__ b) {
    int tid = threadIdx.x;          // 256
    int warp = tid >> 5;
    int lane = tid & 31;
    int grp = lane >> 3;            // 0..3: node within warp
    int sub = lane & 7;             // 0..7: column octet
    int n = (blockIdx.x * 8 + warp) * 4 + grp;   // 3125 * 32 = 100000 exactly

    u64 cd = g_cd[n];
    float dg = decode_deg(cd);
    float dinv = (dg > 0.f) ? rsqrtf(dg) : 0.f;
    int cnt = decode_cnt(cd);
    int nb = (cnt + 7) >> 3;
    int maxnb = __reduce_max_sync(0xffffffffu, nb);

    const char* hwb = reinterpret_cast<const char*>(g_hw);
    int coff = sub * 16;            // byte offset of this lane's 8 halfs

    // self term (dinv-scaled)
    uint4 sv = __ldg(reinterpret_cast<const uint4*>(hwb + n * 128 + coff));
    float2 a0 = __half22float2(*reinterpret_cast<__half2*>(&sv.x));
    float2 a1 = __half22float2(*reinterpret_cast<__half2*>(&sv.y));
    float2 a2 = __half22float2(*reinterpret_cast<__half2*>(&sv.z));
    float2 a3 = __half22float2(*reinterpret_cast<__half2*>(&sv.w));

    const int4* q = reinterpret_cast<const int4*>(&g_csr[n << 6]);

    for (int ib = 0; ib < maxnb; ib++) {
        if (ib < nb) {
            int4 p0 = __ldg(&q[ib * 4 + 0]);
            int4 p1 = __ldg(&q[ib * 4 + 1]);
            int4 p2 = __ldg(&q[ib * 4 + 2]);
            int4 p3 = __ldg(&q[ib * 4 + 3]);
            uint4 v0 = __ldg(reinterpret_cast<const uint4*>(hwb + p0.x * 128 + coff));
            uint4 v1 = __ldg(reinterpret_cast<const uint4*>(hwb + p0.z * 128 + coff));
            uint4 v2 = __ldg(reinterpret_cast<const uint4*>(hwb + p1.x * 128 + coff));
            uint4 v3 = __ldg(reinterpret_cast<const uint4*>(hwb + p1.z * 128 + coff));
            uint4 v4 = __ldg(reinterpret_cast<const uint4*>(hwb + p2.x * 128 + coff));
            uint4 v5 = __ldg(reinterpret_cast<const uint4*>(hwb + p2.z * 128 + coff));
            uint4 v6 = __ldg(reinterpret_cast<const uint4*>(hwb + p3.x * 128 + coff));
            uint4 v7 = __ldg(reinterpret_cast<const uint4*>(hwb + p3.z * 128 + coff));
            __half2 z = __float2half2_rn(0.f);
            __half2 s0 = z, s1 = z, s2 = z, s3 = z;
            edge8(v0, p0.y, s0, s1, s2, s3);
            edge8(v1, p0.w, s0, s1, s2, s3);
            edge8(v2, p1.y, s0, s1, s2, s3);
            edge8(v3, p1.w, s0, s1, s2, s3);
            edge8(v4, p2.y, s0, s1, s2, s3);
            edge8(v5, p2.w, s0, s1, s2, s3);
            edge8(v6, p3.y, s0, s1, s2, s3);
            edge8(v7, p3.w, s0, s1, s2, s3);
            float2 f0 = __half22float2(s0);
            float2 f1 = __half22float2(s1);
            float2 f2 = __half22float2(s2);
            float2 f3 = __half22float2(s3);
            a0.x += f0.x; a0.y += f0.y;
            a1.x += f1.x; a1.y += f1.y;
            a2.x += f2.x; a2.y += f2.y;
            a3.x += f3.x; a3.y += f3.y;
        }
    }

    const float4* b4 = reinterpret_cast<const float4*>(b);
    float4 bb0 = b4[sub * 2];
    float4 bb1 = b4[sub * 2 + 1];
    a0.x = fmaxf(fmaf(a0.x, dinv, bb0.x), 0.f);
    a0.y = fmaxf(fmaf(a0.y, dinv, bb0.y), 0.f);
    a1.x = fmaxf(fmaf(a1.x, dinv, bb0.z), 0.f);
    a1.y = fmaxf(fmaf(a1.y, dinv, bb0.w), 0.f);
    a2.x = fmaxf(fmaf(a2.x, dinv, bb1.x), 0.f);
    a2.y = fmaxf(fmaf(a2.y, dinv, bb1.y), 0.f);
    a3.x = fmaxf(fmaf(a3.x, dinv, bb1.z), 0.f);
    a3.y = fmaxf(fmaf(a3.y, dinv, bb1.w), 0.f);
    __half2 o0 = __floats2half2_rn(a0.x, a0.y);
    __half2 o1 = __floats2half2_rn(a1.x, a1.y);
    __half2 o2 = __floats2half2_rn(a2.x, a2.y);
    __half2 o3 = __floats2half2_rn(a3.x, a3.y);
    uint4 ov = make_uint4(*reinterpret_cast<uint32_t*>(&o0), *reinterpret_cast<uint32_t*>(&o1),
                          *reinterpret_cast<uint32_t*>(&o2), *reinterpret_cast<uint32_t*>(&o3));
    *reinterpret_cast<uint4*>(reinterpret_cast<char*>(g_h) + n * 128 + coff) = ov;
}

// mean pool (batch sorted): one block per graph; h is fp16
__global__ void k_pool(const int* __restrict__ batch, float* __restrict__ out) {
    __shared__ float sh[8][64];
    int g = blockIdx.x;
    int tid = threadIdx.x;   // 256
    int lo = 0, hi = Nn;
    while (lo < hi) { int mid = (lo + hi) >> 1; if (batch[mid] < g) lo = mid + 1; else hi = mid; }
    int start = lo;
    lo = start; hi = Nn;
    while (lo < hi) { int mid = (lo + hi) >> 1; if (batch[mid] < g + 1) lo = mid + 1; else hi = mid; }
    int end = lo;
    int c2 = tid & 31;
    int r = tid >> 5;
    const __half2* h2 = reinterpret_cast<const __half2*>(g_h);
    float2 acc = make_float2(0.f, 0.f);
    for (int node = start + r; node < end; node += 8) {
        float2 v = __half22float2(h2[node * 32 + c2]);
        acc.x += v.x; acc.y += v.y;
    }
    sh[r][c2 * 2] = acc.x;
    sh[r][c2 * 2 + 1] = acc.y;
    __syncthreads();
    if (tid < 64) {
        float su = 0.f;
        #pragma unroll
        for (int k = 0; k < 8; k++) su += sh[k][tid];
        float cnt = (float)(end - start);
        out[g * 64 + tid] = su / fmaxf(cnt, 1.0f);
    }
}

extern "C" void kernel_launch(void* const* d_in, const int* in_sizes, int n_in,
                              void* d_out, int out_size) {
    const float* x       = (const float*)d_in[0];
    const int*   mapping = (const int*)d_in[1];
    const int*   ei      = (const int*)d_in[2];
    const float* ew      = (const float*)d_in[3];
    const int*   batch   = (const int*)d_in[4];
    const float* emb     = (const float*)d_in[5];
    const float* W0      = (const float*)d_in[6];
    const float* b0      = (const float*)d_in[7];
    const float* W1      = (const float*)d_in[8];
    const float* b1      = (const float*)d_in[9];
    float* out = (float*)d_out;

    const int T = 256;
    k_zero<<<(Nn + T - 1) / T, T>>>(W0, W1);
    k_place<<<(Ee + T - 1) / T, T>>>(ei, ew);
    k_pad<<<(Nn * 8 + T - 1) / T, T>>>();

    int gemmBlocks = (Nn + 63) / 64;       // 1563
    int gatherBlocks = Nn / 32;            // 3125, exact
    k_gemm0<<<gemmBlocks, 128>>>(x, mapping, emb);
    k_gather<<<gatherBlocks, T>>>(b0);

    k_gemm1<<<gemmBlocks, 128>>>();
    k_gather<<<gatherBlocks, T>>>(b1);

    k_pool<<<Gg, T>>>(batch, out);
}